// round 7
// baseline (speedup 1.0000x reference)
#include <cuda_runtime.h>
#include <cstdint>
#include <math.h>

#define NTOK 8192
#define CDIM 768
#define HDIM 3072
#define H2   (2*HDIM)
#define NEXP 16
#define TOPK 4
#define TILE_M 64
#define MAX_TILES 656
#define MAX_ROWS (MAX_TILES*TILE_M)

#define KC 16
#define STAGES 4
#define BLK_N 256                  // gemm cols per CTA
#define FC1_NOUT 128               // swiglu outputs per CTA
#define FC1_COLS (HDIM/FC1_NOUT)   // 24
#define FC2_COLS (CDIM/BLK_N)      // 3
#define A_STG 1024                 // floats per stage: 64*16
#define B_STG 4096                 // 16*256
#define STG_FLOATS (A_STG + B_STG)
#define FC_SMEM (STAGES*STG_FLOATS*4)   // 80KB -> 2 CTAs/SM

// ------------------- device scratch -------------------
__device__ float g_xr[(size_t)NTOK*CDIM];
__device__ float g_wfc[(size_t)(NEXP+1)*CDIM*H2];
__device__ float g_wpj[(size_t)(NEXP+1)*HDIM*CDIM];
__device__ float g_act[(size_t)MAX_ROWS*HDIM];
__device__ float g_part[(size_t)MAX_ROWS*CDIM];
__device__ int   g_row_token[MAX_ROWS];
__device__ float g_row_weight[MAX_ROWS];
__device__ int   g_tok_rows[NTOK*(TOPK+1)];
__device__ int   g_counts[NEXP];
__device__ int   g_cursor[NEXP];
__device__ int   g_offset[NEXP+1];
__device__ int   g_tile_expert[MAX_TILES];
__device__ int   g_tile_row0[MAX_TILES];
__device__ int   g_num_tiles;
__device__ int   g_topi[NTOK*TOPK];
__device__ float g_topw[NTOK*TOPK];

// ------------------- helpers -------------------
__device__ __forceinline__ float to_tf32(float x){
    uint32_t u; asm("cvt.rna.tf32.f32 %0, %1;" : "=r"(u) : "f"(x));
    return __uint_as_float(u);
}
__device__ __forceinline__ float silu_f(float x){ return x / (1.0f + expf(-x)); }

__device__ __forceinline__ uint32_t smem_u32(const void* p){
    uint32_t a;
    asm("{ .reg .u64 t; cvta.to.shared.u64 t, %1; cvt.u32.u64 %0, t; }" : "=r"(a) : "l"(p));
    return a;
}

#define CP16(dst, src) \
    asm volatile("cp.async.cg.shared.global [%0], [%1], 16;" :: "r"(dst), "l"(src))
#define CP_COMMIT() asm volatile("cp.async.commit_group;")

__device__ __forceinline__ void mma_tf32(float* d, const uint32_t* a, const uint32_t* b){
    asm volatile(
        "mma.sync.aligned.m16n8k8.row.col.f32.tf32.tf32.f32 "
        "{%0,%1,%2,%3}, {%4,%5,%6,%7}, {%8,%9}, {%0,%1,%2,%3};"
        : "+f"(d[0]), "+f"(d[1]), "+f"(d[2]), "+f"(d[3])
        : "r"(a[0]), "r"(a[1]), "r"(a[2]), "r"(a[3]), "r"(b[0]), "r"(b[1]));
}

// ------------------- prep: round x + all weights to tf32, init state -------------
__global__ void k_prep(const float* __restrict__ x,
                       const float* __restrict__ wfc_sh,
                       const float* __restrict__ wfc_ex,
                       const float* __restrict__ wpj_sh,
                       const float* __restrict__ wpj_ex){
    int i0 = blockIdx.x*blockDim.x + threadIdx.x;
    int stride = gridDim.x*blockDim.x;
    const size_t NFC = (size_t)CDIM*H2;
    const size_t NPJ = (size_t)HDIM*CDIM;

    for (size_t i = i0; i < (size_t)NTOK*CDIM; i += stride) g_xr[i] = to_tf32(x[i]);
    for (size_t i = i0; i < (size_t)NEXP*NFC;  i += stride) g_wfc[i] = to_tf32(wfc_ex[i]);
    for (size_t i = i0; i < NFC;               i += stride) g_wfc[(size_t)NEXP*NFC + i] = to_tf32(wfc_sh[i]);
    for (size_t i = i0; i < (size_t)NEXP*NPJ;  i += stride) g_wpj[i] = to_tf32(wpj_ex[i]);
    for (size_t i = i0; i < NPJ;               i += stride) g_wpj[(size_t)NEXP*NPJ + i] = to_tf32(wpj_sh[i]);

    for (int i = i0; i < MAX_ROWS; i += stride) g_row_token[i] = 0;
    if (i0 < NEXP) g_counts[i0] = 0;
}

// ------------------- gate: logits, sigmoid, top-4, counts ----------------
__global__ void k_gate(const float* __restrict__ x,
                       const float* __restrict__ wg,
                       const float* __restrict__ bias){
    int warp = (blockIdx.x*blockDim.x + threadIdx.x) >> 5;
    int lane = threadIdx.x & 31;
    if (warp >= NTOK) return;
    const float* xr = x + (size_t)warp*CDIM;

    int e = lane & 15, half = lane >> 4;
    float acc = 0.0f;
    int c0 = half*(CDIM/2);
    for (int c = c0; c < c0 + CDIM/2; ++c) acc += xr[c]*wg[c*NEXP + e];
    acc += __shfl_down_sync(0xFFFFFFFFu, acc, 16);

    float gate = -1.0f;
    if (lane < 16) gate = 1.0f/(1.0f + expf(-(acc + bias[e])));

    int rank = 0;
    #pragma unroll
    for (int j = 0; j < 16; ++j){
        float gj = __shfl_sync(0xFFFFFFFFu, gate, j);
        if (lane < 16) rank += (gj > gate) || (gj == gate && j < e);
    }
    bool sel = (lane < 16) && (rank < TOPK);
    float sv = sel ? gate : 0.0f;
    #pragma unroll
    for (int o = 8; o >= 1; o >>= 1) sv += __shfl_xor_sync(0xFFFFFFFFu, sv, o);
    unsigned ballot = __ballot_sync(0xFFFFFFFFu, sel);
    if (sel){
        int kidx = __popc(ballot & ((1u << lane) - 1u));
        g_topi[warp*TOPK + kidx] = e;
        g_topw[warp*TOPK + kidx] = gate/sv;
        atomicAdd(&g_counts[e], 1);
    }
}

// ------------------- scan + fill fused (single CTA) ----------------
__global__ void __launch_bounds__(1024, 1) k_scanfill(){
    if (threadIdx.x == 0){
        int off = 0, nt = 0;
        for (int e = 0; e <= NEXP; ++e){
            int cnt = (e < NEXP) ? g_counts[e] : NTOK;
            g_offset[e] = off;
            if (e < NEXP) g_cursor[e] = off;
            int tiles = (cnt + TILE_M - 1)/TILE_M;
            for (int i = 0; i < tiles; ++i){
                g_tile_expert[nt] = e;
                g_tile_row0[nt] = off + i*TILE_M;
                nt++;
            }
            off += tiles*TILE_M;
        }
        g_num_tiles = nt;
    }
    __syncthreads();
    for (int idx = threadIdx.x; idx < NTOK*(TOPK+1); idx += 1024){
        int t = idx/(TOPK+1), j = idx%(TOPK+1);
        if (j < TOPK){
            int e = g_topi[t*TOPK + j];
            float w = g_topw[t*TOPK + j];
            int r = atomicAdd(&g_cursor[e], 1);
            g_row_token[r] = t;
            g_row_weight[r] = w;
            g_tok_rows[t*(TOPK+1) + j] = r;
        } else {
            int r = g_offset[NEXP] + t;
            g_row_token[r] = t;
            g_row_weight[r] = 1.0f;
            g_tok_rows[t*(TOPK+1) + j] = r;
        }
    }
}

// ------------------- FC1: swiglu(Xg @ Wfc), M=64 x N=256, 256 thr, 2 CTA/SM ------
__global__ void __launch_bounds__(256, 2) k_fc1(){
    int bx = blockIdx.x;
    int tile = bx / FC1_COLS, jb = (bx % FC1_COLS)*FC1_NOUT;
    if (tile >= g_num_tiles) return;
    int e = g_tile_expert[tile], row0 = g_tile_row0[tile];
    const float* wbase = g_wfc + (size_t)e*CDIM*H2;

    extern __shared__ float sm[];
    uint32_t sb = smem_u32(sm);

    int tid = threadIdx.x, lane = tid & 31, w = tid >> 5;
    int wm = w & 1, wn = w >> 1;          // 2 M-warps x 4 N-warps
    int m0 = wm*32, n0 = wn*64;
    int r = lane >> 2, c = lane & 3;

    // cp.async: 1 A chunk + 4 B chunks per thread
    int am = tid >> 2, akc = tid & 3;     // am 0..63
    int tokA = g_row_token[row0 + am];
    const float* asrc = g_xr + (size_t)tokA*CDIM + akc*4;
    uint32_t adst = (uint32_t)(am*16 + ((akc*4) ^ (4*((am >> 1) & 3))))*4;

    const float* bsrc[4]; uint32_t bdst[4];
    #pragma unroll
    for (int i = 0; i < 4; i++){
        int p = tid + i*256;
        int bk = p >> 6, c0 = (p & 63)*4;
        int grp = c0 >> 3, off = c0 & 7;
        int srccol = (grp & 1) ? (HDIM + jb + (grp >> 1)*8 + off)
                               : (jb + (grp >> 1)*8 + off);
        bsrc[i] = wbase + (size_t)bk*H2 + srccol;
        bdst[i] = (uint32_t)(A_STG + bk*256 + (c0 ^ (8*(bk & 3))))*4;
    }

    #pragma unroll
    for (int s = 0; s < STAGES-1; s++){
        uint32_t so = sb + s*(STG_FLOATS*4);
        CP16(so + adst, asrc + s*KC);
        #pragma unroll
        for (int i = 0; i < 4; i++)
            CP16(so + bdst[i], bsrc[i] + (size_t)s*KC*H2);
        CP_COMMIT();
    }

    float acc[2][8][4];
    #pragma unroll
    for (int i = 0; i < 2; i++)
        #pragma unroll
        for (int j = 0; j < 8; j++)
            #pragma unroll
            for (int q = 0; q < 4; q++) acc[i][j][q] = 0.0f;

    int xa = 4*(r >> 1);
    int ak[2][2];
    ak[0][0] = c ^ xa;        ak[0][1] = (c + 4) ^ xa;
    ak[1][0] = (8 + c) ^ xa;  ak[1][1] = (12 + c) ^ xa;
    int arow[4];
    #pragma unroll
    for (int j = 0; j < 4; j++) arow[j] = (m0 + j*8 + r)*16;
    int nx[8];
    #pragma unroll
    for (int ni = 0; ni < 8; ni++) nx[ni] = (n0 + r + 8*ni) ^ (8*c);
    int bkrow[2][2];
    bkrow[0][0] = A_STG + (c)*256;      bkrow[0][1] = A_STG + (c + 4)*256;
    bkrow[1][0] = A_STG + (8 + c)*256;  bkrow[1][1] = A_STG + (12 + c)*256;

    const int nK = CDIM/KC;   // 48
    for (int ks = 0; ks < nK; ks++){
        asm volatile("cp.async.wait_group %0;" :: "n"(STAGES-2) : "memory");
        __syncthreads();
        int t = ks + STAGES - 1;
        if (t < nK){
            uint32_t so = sb + (t % STAGES)*(STG_FLOATS*4);
            CP16(so + adst, asrc + t*KC);
            #pragma unroll
            for (int i = 0; i < 4; i++)
                CP16(so + bdst[i], bsrc[i] + (size_t)t*KC*H2);
        }
        CP_COMMIT();

        const uint32_t* As = (const uint32_t*)sm + (ks % STAGES)*STG_FLOATS;
        #pragma unroll
        for (int kb = 0; kb < 2; kb++){
            uint32_t a[2][4];
            #pragma unroll
            for (int mi = 0; mi < 2; mi++){
                a[mi][0] = As[arow[2*mi]     + ak[kb][0]];
                a[mi][1] = As[arow[2*mi + 1] + ak[kb][0]];
                a[mi][2] = As[arow[2*mi]     + ak[kb][1]];
                a[mi][3] = As[arow[2*mi + 1] + ak[kb][1]];
            }
            uint32_t b[8][2];
            #pragma unroll
            for (int ni = 0; ni < 8; ni++){
                b[ni][0] = As[bkrow[kb][0] + nx[ni]];
                b[ni][1] = As[bkrow[kb][1] + nx[ni]];
            }
            #pragma unroll
            for (int mi = 0; mi < 2; mi++)
                #pragma unroll
                for (int ni = 0; ni < 8; ni++)
                    mma_tf32(acc[mi][ni], a[mi], b[ni]);
        }
    }

    // epilogue: swiglu pairs (ni even = gate, ni+1 = val)
    int c2 = (lane & 3)*2;
    #pragma unroll
    for (int mi = 0; mi < 2; mi++){
        int ra = row0 + m0 + mi*16 + r;
        #pragma unroll
        for (int fe = 0; fe < 8; fe += 2){
            float* ag = acc[mi][fe];
            float* av = acc[mi][fe + 1];
            int ocol = jb + (4*wn + (fe >> 1))*8 + c2;
            float2 o0, o1;
            o0.x = to_tf32(silu_f(ag[0])*av[0]);
            o0.y = to_tf32(silu_f(ag[1])*av[1]);
            o1.x = to_tf32(silu_f(ag[2])*av[2]);
            o1.y = to_tf32(silu_f(ag[3])*av[3]);
            *(float2*)(g_act + (size_t)ra*HDIM + ocol) = o0;
            *(float2*)(g_act + (size_t)(ra + 8)*HDIM + ocol) = o1;
        }
    }
}

// ------------------- FC2: act @ Wproj -> g_part, M=64 x N=256 -------------------
__global__ void __launch_bounds__(256, 2) k_fc2(){
    int bx = blockIdx.x;
    int tile = bx / FC2_COLS, jb = (bx % FC2_COLS)*BLK_N;
    if (tile >= g_num_tiles) return;
    int e = g_tile_expert[tile], row0 = g_tile_row0[tile];
    const float* wbase = g_wpj + (size_t)e*HDIM*CDIM;

    extern __shared__ float sm[];
    uint32_t sb = smem_u32(sm);

    int tid = threadIdx.x, lane = tid & 31, w = tid >> 5;
    int wm = w & 1, wn = w >> 1;
    int m0 = wm*32, n0 = wn*64;
    int r = lane >> 2, c = lane & 3;

    int am = tid >> 2, akc = tid & 3;
    const float* asrc = g_act + (size_t)(row0 + am)*HDIM + akc*4;
    uint32_t adst = (uint32_t)(am*16 + ((akc*4) ^ (4*((am >> 1) & 3))))*4;

    const float* bsrc[4]; uint32_t bdst[4];
    #pragma unroll
    for (int i = 0; i < 4; i++){
        int p = tid + i*256;
        int bk = p >> 6, c0 = (p & 63)*4;
        bsrc[i] = wbase + (size_t)bk*CDIM + jb + c0;
        bdst[i] = (uint32_t)(A_STG + bk*256 + (c0 ^ (8*(bk & 3))))*4;
    }

    #pragma unroll
    for (int s = 0; s < STAGES-1; s++){
        uint32_t so = sb + s*(STG_FLOATS*4);
        CP16(so + adst, asrc + s*KC);
        #pragma unroll
        for (int i = 0; i < 4; i++)
            CP16(so + bdst[i], bsrc[i] + (size_t)s*KC*CDIM);
        CP_COMMIT();
    }

    float acc[2][8][4];
    #pragma unroll
    for (int i = 0; i < 2; i++)
        #pragma unroll
        for (int j = 0; j < 8; j++)
            #pragma unroll
            for (int q = 0; q < 4; q++) acc[i][j][q] = 0.0f;

    int xa = 4*(r >> 1);
    int ak[2][2];
    ak[0][0] = c ^ xa;        ak[0][1] = (c + 4) ^ xa;
    ak[1][0] = (8 + c) ^ xa;  ak[1][1] = (12 + c) ^ xa;
    int arow[4];
    #pragma unroll
    for (int j = 0; j < 4; j++) arow[j] = (m0 + j*8 + r)*16;
    int nx[8];
    #pragma unroll
    for (int ni = 0; ni < 8; ni++) nx[ni] = (n0 + r + 8*ni) ^ (8*c);
    int bkrow[2][2];
    bkrow[0][0] = A_STG + (c)*256;      bkrow[0][1] = A_STG + (c + 4)*256;
    bkrow[1][0] = A_STG + (8 + c)*256;  bkrow[1][1] = A_STG + (12 + c)*256;

    const int nK = HDIM/KC;   // 192
    for (int ks = 0; ks < nK; ks++){
        asm volatile("cp.async.wait_group %0;" :: "n"(STAGES-2) : "memory");
        __syncthreads();
        int t = ks + STAGES - 1;
        if (t < nK){
            uint32_t so = sb + (t % STAGES)*(STG_FLOATS*4);
            CP16(so + adst, asrc + t*KC);
            #pragma unroll
            for (int i = 0; i < 4; i++)
                CP16(so + bdst[i], bsrc[i] + (size_t)t*KC*CDIM);
        }
        CP_COMMIT();

        const uint32_t* As = (const uint32_t*)sm + (ks % STAGES)*STG_FLOATS;
        #pragma unroll
        for (int kb = 0; kb < 2; kb++){
            uint32_t a[2][4];
            #pragma unroll
            for (int mi = 0; mi < 2; mi++){
                a[mi][0] = As[arow[2*mi]     + ak[kb][0]];
                a[mi][1] = As[arow[2*mi + 1] + ak[kb][0]];
                a[mi][2] = As[arow[2*mi]     + ak[kb][1]];
                a[mi][3] = As[arow[2*mi + 1] + ak[kb][1]];
            }
            uint32_t b[8][2];
            #pragma unroll
            for (int ni = 0; ni < 8; ni++){
                b[ni][0] = As[bkrow[kb][0] + nx[ni]];
                b[ni][1] = As[bkrow[kb][1] + nx[ni]];
            }
            #pragma unroll
            for (int mi = 0; mi < 2; mi++)
                #pragma unroll
                for (int ni = 0; ni < 8; ni++)
                    mma_tf32(acc[mi][ni], a[mi], b[ni]);
        }
    }

    int c2 = (lane & 3)*2;
    #pragma unroll
    for (int mi = 0; mi < 2; mi++){
        int ra = row0 + m0 + mi*16 + r;
        #pragma unroll
        for (int ni = 0; ni < 8; ni++){
            int ocol = jb + n0 + ni*8 + c2;
            float2 o0, o1;
            o0.x = acc[mi][ni][0]; o0.y = acc[mi][ni][1];
            o1.x = acc[mi][ni][2]; o1.y = acc[mi][ni][3];
            *(float2*)(g_part + (size_t)ra*CDIM + ocol) = o0;
            *(float2*)(g_part + (size_t)(ra + 8)*CDIM + ocol) = o1;
        }
    }
}

// ------------------- gather: out[t] = sum_j w_j * part[r_j] -------------------
__global__ void k_gather(float* __restrict__ out){
    __shared__ int rs[TOPK+1];
    __shared__ float ws[TOPK+1];
    int t = blockIdx.x;
    if (threadIdx.x < TOPK+1){
        int r = g_tok_rows[t*(TOPK+1) + threadIdx.x];
        rs[threadIdx.x] = r;
        ws[threadIdx.x] = g_row_weight[r];
    }
    __syncthreads();
    int c = threadIdx.x*4;
    float4 acc = make_float4(0.f, 0.f, 0.f, 0.f);
    #pragma unroll
    for (int j = 0; j < TOPK+1; j++){
        const float4 p = *(const float4*)(g_part + (size_t)rs[j]*CDIM + c);
        float w = ws[j];
        acc.x += w*p.x; acc.y += w*p.y; acc.z += w*p.z; acc.w += w*p.w;
    }
    *(float4*)(out + (size_t)t*CDIM + c) = acc;
}

// ------------------- launch -------------------
extern "C" void kernel_launch(void* const* d_in, const int* in_sizes, int n_in,
                              void* d_out, int out_size){
    const float* x              = (const float*)d_in[0];
    const float* w_shared_fc    = (const float*)d_in[1];
    const float* w_shared_proj  = (const float*)d_in[2];
    const float* w_experts_fc   = (const float*)d_in[3];
    const float* w_experts_proj = (const float*)d_in[4];
    const float* w_gate         = (const float*)d_in[5];
    const float* expert_bias    = (const float*)d_in[6];
    float* out = (float*)d_out;

    cudaFuncSetAttribute(k_fc1, cudaFuncAttributeMaxDynamicSharedMemorySize, FC_SMEM);
    cudaFuncSetAttribute(k_fc2, cudaFuncAttributeMaxDynamicSharedMemorySize, FC_SMEM);

    // launch #1: all rounding + init fused
    k_prep<<<2368, 256>>>(x, w_shared_fc, w_experts_fc, w_shared_proj, w_experts_proj);
    // launch #2
    k_gate<<<NTOK/8, 256>>>(x, w_gate, expert_bias);
    // launch #3
    k_scanfill<<<1, 1024>>>();
    // launch #4  <- ncu captures this one
    k_fc1<<<MAX_TILES*FC1_COLS, 256, FC_SMEM>>>();
    // launch #5
    k_fc2<<<MAX_TILES*FC2_COLS, 256, FC_SMEM>>>();
    // launch #6
    k_gather<<<NTOK, CDIM/4>>>(out);
}

// round 8
// speedup vs baseline: 1.0169x; 1.0169x over previous
#include <cuda_runtime.h>
#include <cstdint>
#include <math.h>

#define NTOK 8192
#define CDIM 768
#define HDIM 3072
#define H2   (2*HDIM)
#define NEXP 16
#define TOPK 4
#define TILE_M 128
#define MAX_TILES 336
#define MAX_ROWS (MAX_TILES*TILE_M)

#define KC 16
#define STAGES 4
#define BLK_N 256                  // gemm cols per CTA
#define FC1_NOUT 128               // swiglu outputs per CTA
#define FC1_COLS (HDIM/FC1_NOUT)   // 24
#define FC2_COLS (CDIM/BLK_N)      // 3
#define A_STG 2048                 // floats per stage: 128*16
#define B_STG 4096                 // 16*256
#define STG_FLOATS (A_STG + B_STG)
#define FC_SMEM (STAGES*STG_FLOATS*4)   // 96KB, 1 CTA/SM

// ------------------- device scratch -------------------
__device__ float g_xr[(size_t)NTOK*CDIM];
__device__ float g_wfc[(size_t)(NEXP+1)*CDIM*H2];
__device__ float g_wpj[(size_t)(NEXP+1)*HDIM*CDIM];
__device__ float g_act[(size_t)MAX_ROWS*HDIM];
__device__ float g_part[(size_t)MAX_ROWS*CDIM];
__device__ int   g_row_token[MAX_ROWS];
__device__ float g_row_weight[MAX_ROWS];
__device__ int   g_tok_rows[NTOK*(TOPK+1)];
__device__ int   g_counts[NEXP];
__device__ int   g_cursor[NEXP];
__device__ int   g_offset[NEXP+1];
__device__ int   g_tile_expert[MAX_TILES];
__device__ int   g_tile_row0[MAX_TILES];
__device__ int   g_num_tiles;
__device__ int   g_topi[NTOK*TOPK];
__device__ float g_topw[NTOK*TOPK];

// ------------------- helpers -------------------
__device__ __forceinline__ float to_tf32(float x){
    uint32_t u; asm("cvt.rna.tf32.f32 %0, %1;" : "=r"(u) : "f"(x));
    return __uint_as_float(u);
}
__device__ __forceinline__ float silu_f(float x){ return x / (1.0f + expf(-x)); }

__device__ __forceinline__ uint32_t smem_u32(const void* p){
    uint32_t a;
    asm("{ .reg .u64 t; cvta.to.shared.u64 t, %1; cvt.u32.u64 %0, t; }" : "=r"(a) : "l"(p));
    return a;
}

#define CP16(dst, src) \
    asm volatile("cp.async.cg.shared.global [%0], [%1], 16;" :: "r"(dst), "l"(src))
#define CP_COMMIT() asm volatile("cp.async.commit_group;")

__device__ __forceinline__ void mma_tf32(float* d, const uint32_t* a, const uint32_t* b){
    asm volatile(
        "mma.sync.aligned.m16n8k8.row.col.f32.tf32.tf32.f32 "
        "{%0,%1,%2,%3}, {%4,%5,%6,%7}, {%8,%9}, {%0,%1,%2,%3};"
        : "+f"(d[0]), "+f"(d[1]), "+f"(d[2]), "+f"(d[3])
        : "r"(a[0]), "r"(a[1]), "r"(a[2]), "r"(a[3]), "r"(b[0]), "r"(b[1]));
}

// ------------------- prep: round x + all weights to tf32, init state -------------
__global__ void k_prep(const float* __restrict__ x,
                       const float* __restrict__ wfc_sh,
                       const float* __restrict__ wfc_ex,
                       const float* __restrict__ wpj_sh,
                       const float* __restrict__ wpj_ex){
    int i0 = blockIdx.x*blockDim.x + threadIdx.x;
    int stride = gridDim.x*blockDim.x;
    const size_t NFC = (size_t)CDIM*H2;
    const size_t NPJ = (size_t)HDIM*CDIM;

    for (size_t i = i0; i < (size_t)NTOK*CDIM; i += stride) g_xr[i] = to_tf32(x[i]);
    for (size_t i = i0; i < (size_t)NEXP*NFC;  i += stride) g_wfc[i] = to_tf32(wfc_ex[i]);
    for (size_t i = i0; i < NFC;               i += stride) g_wfc[(size_t)NEXP*NFC + i] = to_tf32(wfc_sh[i]);
    for (size_t i = i0; i < (size_t)NEXP*NPJ;  i += stride) g_wpj[i] = to_tf32(wpj_ex[i]);
    for (size_t i = i0; i < NPJ;               i += stride) g_wpj[(size_t)NEXP*NPJ + i] = to_tf32(wpj_sh[i]);

    for (int i = i0; i < MAX_ROWS; i += stride) g_row_token[i] = 0;
    if (i0 < NEXP) g_counts[i0] = 0;
}

// ------------------- gate: logits, sigmoid, top-4, counts ----------------
__global__ void k_gate(const float* __restrict__ x,
                       const float* __restrict__ wg,
                       const float* __restrict__ bias){
    int warp = (blockIdx.x*blockDim.x + threadIdx.x) >> 5;
    int lane = threadIdx.x & 31;
    if (warp >= NTOK) return;
    const float* xr = x + (size_t)warp*CDIM;

    int e = lane & 15, half = lane >> 4;
    float acc = 0.0f;
    int c0 = half*(CDIM/2);
    for (int c = c0; c < c0 + CDIM/2; ++c) acc += xr[c]*wg[c*NEXP + e];
    acc += __shfl_down_sync(0xFFFFFFFFu, acc, 16);

    float gate = -1.0f;
    if (lane < 16) gate = 1.0f/(1.0f + expf(-(acc + bias[e])));

    int rank = 0;
    #pragma unroll
    for (int j = 0; j < 16; ++j){
        float gj = __shfl_sync(0xFFFFFFFFu, gate, j);
        if (lane < 16) rank += (gj > gate) || (gj == gate && j < e);
    }
    bool sel = (lane < 16) && (rank < TOPK);
    float sv = sel ? gate : 0.0f;
    #pragma unroll
    for (int o = 8; o >= 1; o >>= 1) sv += __shfl_xor_sync(0xFFFFFFFFu, sv, o);
    unsigned ballot = __ballot_sync(0xFFFFFFFFu, sel);
    if (sel){
        int kidx = __popc(ballot & ((1u << lane) - 1u));
        g_topi[warp*TOPK + kidx] = e;
        g_topw[warp*TOPK + kidx] = gate/sv;
        atomicAdd(&g_counts[e], 1);
    }
}

// ------------------- scan + fill fused (single CTA) ----------------
__global__ void __launch_bounds__(1024, 1) k_scanfill(){
    if (threadIdx.x == 0){
        int off = 0, nt = 0;
        for (int e = 0; e <= NEXP; ++e){
            int cnt = (e < NEXP) ? g_counts[e] : NTOK;
            g_offset[e] = off;
            if (e < NEXP) g_cursor[e] = off;
            int tiles = (cnt + TILE_M - 1)/TILE_M;
            for (int i = 0; i < tiles; ++i){
                g_tile_expert[nt] = e;
                g_tile_row0[nt] = off + i*TILE_M;
                nt++;
            }
            off += tiles*TILE_M;
        }
        g_num_tiles = nt;
    }
    __syncthreads();
    for (int idx = threadIdx.x; idx < NTOK*(TOPK+1); idx += 1024){
        int t = idx/(TOPK+1), j = idx%(TOPK+1);
        if (j < TOPK){
            int e = g_topi[t*TOPK + j];
            float w = g_topw[t*TOPK + j];
            int r = atomicAdd(&g_cursor[e], 1);
            g_row_token[r] = t;
            g_row_weight[r] = w;
            g_tok_rows[t*(TOPK+1) + j] = r;
        } else {
            int r = g_offset[NEXP] + t;
            g_row_token[r] = t;
            g_row_weight[r] = 1.0f;
            g_tok_rows[t*(TOPK+1) + j] = r;
        }
    }
}

// ------------------- FC1: swiglu(Xg @ Wfc), CTA 128x256, warp 64x64 ---------------
// 8 warps (2 M x 4 N), 256 threads, 1 CTA/SM, acc 128 regs/thread
__global__ void __launch_bounds__(256, 1) k_fc1(){
    int bx = blockIdx.x;
    int tile = bx / FC1_COLS, jb = (bx % FC1_COLS)*FC1_NOUT;
    if (tile >= g_num_tiles) return;
    int e = g_tile_expert[tile], row0 = g_tile_row0[tile];
    const float* wbase = g_wfc + (size_t)e*CDIM*H2;

    extern __shared__ float sm[];
    uint32_t sb = smem_u32(sm);

    int tid = threadIdx.x, lane = tid & 31, w = tid >> 5;
    int wm = w & 1, wn = w >> 1;          // 2 M-warps x 4 N-warps
    int m0 = wm*64, n0 = wn*64;
    int r = lane >> 2, c = lane & 3;

    // cp.async: 2 A chunks (rows am, am+64) + 4 B chunks per thread
    int am = tid >> 2, akc = tid & 3;     // am 0..63
    int tokA0 = g_row_token[row0 + am];
    int tokA1 = g_row_token[row0 + am + 64];
    const float* asrc0 = g_xr + (size_t)tokA0*CDIM + akc*4;
    const float* asrc1 = g_xr + (size_t)tokA1*CDIM + akc*4;
    uint32_t adst0 = (uint32_t)(am*16 + ((akc*4) ^ (4*((am >> 1) & 3))))*4;
    uint32_t adst1 = adst0 + 64*16*4;     // row +64: same swizzle phase (period 8)

    const float* bsrc[4]; uint32_t bdst[4];
    #pragma unroll
    for (int i = 0; i < 4; i++){
        int p = tid + i*256;
        int bk = p >> 6, c0 = (p & 63)*4;
        int grp = c0 >> 3, off = c0 & 7;
        int srccol = (grp & 1) ? (HDIM + jb + (grp >> 1)*8 + off)
                               : (jb + (grp >> 1)*8 + off);
        bsrc[i] = wbase + (size_t)bk*H2 + srccol;
        bdst[i] = (uint32_t)(A_STG + bk*256 + (c0 ^ (8*(bk & 3))))*4;
    }

    #pragma unroll
    for (int s = 0; s < STAGES-1; s++){
        uint32_t so = sb + s*(STG_FLOATS*4);
        CP16(so + adst0, asrc0 + s*KC);
        CP16(so + adst1, asrc1 + s*KC);
        #pragma unroll
        for (int i = 0; i < 4; i++)
            CP16(so + bdst[i], bsrc[i] + (size_t)s*KC*H2);
        CP_COMMIT();
    }

    float acc[4][8][4];
    #pragma unroll
    for (int i = 0; i < 4; i++)
        #pragma unroll
        for (int j = 0; j < 8; j++)
            #pragma unroll
            for (int q = 0; q < 4; q++) acc[i][j][q] = 0.0f;

    int xa = 4*(r >> 1);
    int ak[2][2];
    ak[0][0] = c ^ xa;        ak[0][1] = (c + 4) ^ xa;
    ak[1][0] = (8 + c) ^ xa;  ak[1][1] = (12 + c) ^ xa;
    int arow[8];
    #pragma unroll
    for (int j = 0; j < 8; j++) arow[j] = (m0 + j*8 + r)*16;
    int nx[8];
    #pragma unroll
    for (int ni = 0; ni < 8; ni++) nx[ni] = (n0 + r + 8*ni) ^ (8*c);
    int bkrow[2][2];
    bkrow[0][0] = A_STG + (c)*256;      bkrow[0][1] = A_STG + (c + 4)*256;
    bkrow[1][0] = A_STG + (8 + c)*256;  bkrow[1][1] = A_STG + (12 + c)*256;

    const int nK = CDIM/KC;   // 48
    for (int ks = 0; ks < nK; ks++){
        asm volatile("cp.async.wait_group %0;" :: "n"(STAGES-2) : "memory");
        __syncthreads();
        int t = ks + STAGES - 1;
        if (t < nK){
            uint32_t so = sb + (t % STAGES)*(STG_FLOATS*4);
            CP16(so + adst0, asrc0 + t*KC);
            CP16(so + adst1, asrc1 + t*KC);
            #pragma unroll
            for (int i = 0; i < 4; i++)
                CP16(so + bdst[i], bsrc[i] + (size_t)t*KC*H2);
        }
        CP_COMMIT();

        const uint32_t* As = (const uint32_t*)sm + (ks % STAGES)*STG_FLOATS;
        #pragma unroll
        for (int kb = 0; kb < 2; kb++){
            uint32_t a[4][4];
            #pragma unroll
            for (int mi = 0; mi < 4; mi++){
                a[mi][0] = As[arow[2*mi]     + ak[kb][0]];
                a[mi][1] = As[arow[2*mi + 1] + ak[kb][0]];
                a[mi][2] = As[arow[2*mi]     + ak[kb][1]];
                a[mi][3] = As[arow[2*mi + 1] + ak[kb][1]];
            }
            uint32_t b[8][2];
            #pragma unroll
            for (int ni = 0; ni < 8; ni++){
                b[ni][0] = As[bkrow[kb][0] + nx[ni]];
                b[ni][1] = As[bkrow[kb][1] + nx[ni]];
            }
            #pragma unroll
            for (int mi = 0; mi < 4; mi++)
                #pragma unroll
                for (int ni = 0; ni < 8; ni++)
                    mma_tf32(acc[mi][ni], a[mi], b[ni]);
        }
    }

    // epilogue: swiglu pairs (ni even = gate, ni+1 = val)
    int c2 = (lane & 3)*2;
    #pragma unroll
    for (int mi = 0; mi < 4; mi++){
        int ra = row0 + m0 + mi*16 + r;
        #pragma unroll
        for (int fe = 0; fe < 8; fe += 2){
            float* ag = acc[mi][fe];
            float* av = acc[mi][fe + 1];
            int ocol = jb + (4*wn + (fe >> 1))*8 + c2;
            float2 o0, o1;
            o0.x = to_tf32(silu_f(ag[0])*av[0]);
            o0.y = to_tf32(silu_f(ag[1])*av[1]);
            o1.x = to_tf32(silu_f(ag[2])*av[2]);
            o1.y = to_tf32(silu_f(ag[3])*av[3]);
            *(float2*)(g_act + (size_t)ra*HDIM + ocol) = o0;
            *(float2*)(g_act + (size_t)(ra + 8)*HDIM + ocol) = o1;
        }
    }
}

// ------------------- FC2: act @ Wproj -> g_part, CTA 128x256, warp 64x64 ----------
__global__ void __launch_bounds__(256, 1) k_fc2(){
    int bx = blockIdx.x;
    int tile = bx / FC2_COLS, jb = (bx % FC2_COLS)*BLK_N;
    if (tile >= g_num_tiles) return;
    int e = g_tile_expert[tile], row0 = g_tile_row0[tile];
    const float* wbase = g_wpj + (size_t)e*HDIM*CDIM;

    extern __shared__ float sm[];
    uint32_t sb = smem_u32(sm);

    int tid = threadIdx.x, lane = tid & 31, w = tid >> 5;
    int wm = w & 1, wn = w >> 1;
    int m0 = wm*64, n0 = wn*64;
    int r = lane >> 2, c = lane & 3;

    int am = tid >> 2, akc = tid & 3;
    const float* asrc0 = g_act + (size_t)(row0 + am)*HDIM + akc*4;
    const float* asrc1 = g_act + (size_t)(row0 + am + 64)*HDIM + akc*4;
    uint32_t adst0 = (uint32_t)(am*16 + ((akc*4) ^ (4*((am >> 1) & 3))))*4;
    uint32_t adst1 = adst0 + 64*16*4;

    const float* bsrc[4]; uint32_t bdst[4];
    #pragma unroll
    for (int i = 0; i < 4; i++){
        int p = tid + i*256;
        int bk = p >> 6, c0 = (p & 63)*4;
        bsrc[i] = wbase + (size_t)bk*CDIM + jb + c0;
        bdst[i] = (uint32_t)(A_STG + bk*256 + (c0 ^ (8*(bk & 3))))*4;
    }

    #pragma unroll
    for (int s = 0; s < STAGES-1; s++){
        uint32_t so = sb + s*(STG_FLOATS*4);
        CP16(so + adst0, asrc0 + s*KC);
        CP16(so + adst1, asrc1 + s*KC);
        #pragma unroll
        for (int i = 0; i < 4; i++)
            CP16(so + bdst[i], bsrc[i] + (size_t)s*KC*CDIM);
        CP_COMMIT();
    }

    float acc[4][8][4];
    #pragma unroll
    for (int i = 0; i < 4; i++)
        #pragma unroll
        for (int j = 0; j < 8; j++)
            #pragma unroll
            for (int q = 0; q < 4; q++) acc[i][j][q] = 0.0f;

    int xa = 4*(r >> 1);
    int ak[2][2];
    ak[0][0] = c ^ xa;        ak[0][1] = (c + 4) ^ xa;
    ak[1][0] = (8 + c) ^ xa;  ak[1][1] = (12 + c) ^ xa;
    int arow[8];
    #pragma unroll
    for (int j = 0; j < 8; j++) arow[j] = (m0 + j*8 + r)*16;
    int nx[8];
    #pragma unroll
    for (int ni = 0; ni < 8; ni++) nx[ni] = (n0 + r + 8*ni) ^ (8*c);
    int bkrow[2][2];
    bkrow[0][0] = A_STG + (c)*256;      bkrow[0][1] = A_STG + (c + 4)*256;
    bkrow[1][0] = A_STG + (8 + c)*256;  bkrow[1][1] = A_STG + (12 + c)*256;

    const int nK = HDIM/KC;   // 192
    for (int ks = 0; ks < nK; ks++){
        asm volatile("cp.async.wait_group %0;" :: "n"(STAGES-2) : "memory");
        __syncthreads();
        int t = ks + STAGES - 1;
        if (t < nK){
            uint32_t so = sb + (t % STAGES)*(STG_FLOATS*4);
            CP16(so + adst0, asrc0 + t*KC);
            CP16(so + adst1, asrc1 + t*KC);
            #pragma unroll
            for (int i = 0; i < 4; i++)
                CP16(so + bdst[i], bsrc[i] + (size_t)t*KC*CDIM);
        }
        CP_COMMIT();

        const uint32_t* As = (const uint32_t*)sm + (ks % STAGES)*STG_FLOATS;
        #pragma unroll
        for (int kb = 0; kb < 2; kb++){
            uint32_t a[4][4];
            #pragma unroll
            for (int mi = 0; mi < 4; mi++){
                a[mi][0] = As[arow[2*mi]     + ak[kb][0]];
                a[mi][1] = As[arow[2*mi + 1] + ak[kb][0]];
                a[mi][2] = As[arow[2*mi]     + ak[kb][1]];
                a[mi][3] = As[arow[2*mi + 1] + ak[kb][1]];
            }
            uint32_t b[8][2];
            #pragma unroll
            for (int ni = 0; ni < 8; ni++){
                b[ni][0] = As[bkrow[kb][0] + nx[ni]];
                b[ni][1] = As[bkrow[kb][1] + nx[ni]];
            }
            #pragma unroll
            for (int mi = 0; mi < 4; mi++)
                #pragma unroll
                for (int ni = 0; ni < 8; ni++)
                    mma_tf32(acc[mi][ni], a[mi], b[ni]);
        }
    }

    int c2 = (lane & 3)*2;
    #pragma unroll
    for (int mi = 0; mi < 4; mi++){
        int ra = row0 + m0 + mi*16 + r;
        #pragma unroll
        for (int ni = 0; ni < 8; ni++){
            int ocol = jb + n0 + ni*8 + c2;
            float2 o0, o1;
            o0.x = acc[mi][ni][0]; o0.y = acc[mi][ni][1];
            o1.x = acc[mi][ni][2]; o1.y = acc[mi][ni][3];
            *(float2*)(g_part + (size_t)ra*CDIM + ocol) = o0;
            *(float2*)(g_part + (size_t)(ra + 8)*CDIM + ocol) = o1;
        }
    }
}

// ------------------- gather: out[t] = sum_j w_j * part[r_j] -------------------
__global__ void k_gather(float* __restrict__ out){
    __shared__ int rs[TOPK+1];
    __shared__ float ws[TOPK+1];
    int t = blockIdx.x;
    if (threadIdx.x < TOPK+1){
        int r = g_tok_rows[t*(TOPK+1) + threadIdx.x];
        rs[threadIdx.x] = r;
        ws[threadIdx.x] = g_row_weight[r];
    }
    __syncthreads();
    int c = threadIdx.x*4;
    float4 acc = make_float4(0.f, 0.f, 0.f, 0.f);
    #pragma unroll
    for (int j = 0; j < TOPK+1; j++){
        const float4 p = *(const float4*)(g_part + (size_t)rs[j]*CDIM + c);
        float w = ws[j];
        acc.x += w*p.x; acc.y += w*p.y; acc.z += w*p.z; acc.w += w*p.w;
    }
    *(float4*)(out + (size_t)t*CDIM + c) = acc;
}

// ------------------- launch -------------------
extern "C" void kernel_launch(void* const* d_in, const int* in_sizes, int n_in,
                              void* d_out, int out_size){
    const float* x              = (const float*)d_in[0];
    const float* w_shared_fc    = (const float*)d_in[1];
    const float* w_shared_proj  = (const float*)d_in[2];
    const float* w_experts_fc   = (const float*)d_in[3];
    const float* w_experts_proj = (const float*)d_in[4];
    const float* w_gate         = (const float*)d_in[5];
    const float* expert_bias    = (const float*)d_in[6];
    float* out = (float*)d_out;

    cudaFuncSetAttribute(k_fc1, cudaFuncAttributeMaxDynamicSharedMemorySize, FC_SMEM);
    cudaFuncSetAttribute(k_fc2, cudaFuncAttributeMaxDynamicSharedMemorySize, FC_SMEM);

    // launch #1: all rounding + init fused
    k_prep<<<2368, 256>>>(x, w_shared_fc, w_experts_fc, w_shared_proj, w_experts_proj);
    // launch #2
    k_gate<<<NTOK/8, 256>>>(x, w_gate, expert_bias);
    // launch #3
    k_scanfill<<<1, 1024>>>();
    // launch #4  <- ncu captures this one
    k_fc1<<<MAX_TILES*FC1_COLS, 256, FC_SMEM>>>();
    // launch #5
    k_fc2<<<MAX_TILES*FC2_COLS, 256, FC_SMEM>>>();
    // launch #6
    k_gather<<<NTOK, CDIM/4>>>(out);
}

// round 9
// speedup vs baseline: 1.8889x; 1.8575x over previous
#include <cuda_runtime.h>
#include <cuda_fp16.h>
#include <cstdint>
#include <math.h>

#define NTOK 8192
#define CDIM 768
#define HDIM 3072
#define H2   (2*HDIM)
#define NEXP 16
#define TOPK 4
#define TILE_M 128
#define MAX_TILES 336
#define MAX_ROWS (MAX_TILES*TILE_M)

#define KC 16
#define STAGES 4
#define BLK_N 256
#define FC1_NOUT 128
#define FC1_COLS (HDIM/FC1_NOUT)   // 24
#define FC2_COLS (CDIM/BLK_N)      // 3
#define A_BYTES (128*16*2)         // 4096 per stage
#define B_BYTES (16*256*2)         // 8192 per stage
#define STG_BYTES (A_BYTES + B_BYTES)   // 12288
#define FC_SMEM (STAGES*STG_BYTES)      // 48KB

// ------------------- device scratch -------------------
__device__ __align__(16) __half g_xh[(size_t)NTOK*CDIM];
__device__ __align__(16) __half g_wfc_h[(size_t)(NEXP+1)*CDIM*H2];
__device__ __align__(16) __half g_wpj_h[(size_t)(NEXP+1)*HDIM*CDIM];
__device__ __align__(16) __half g_act[(size_t)MAX_ROWS*HDIM];
__device__ float g_part[(size_t)MAX_ROWS*CDIM];
__device__ int   g_row_token[MAX_ROWS];
__device__ float g_row_weight[MAX_ROWS];
__device__ int   g_tok_rows[NTOK*(TOPK+1)];
__device__ int   g_counts[NEXP];
__device__ int   g_cursor[NEXP];
__device__ int   g_offset[NEXP+1];
__device__ int   g_tile_expert[MAX_TILES];
__device__ int   g_tile_row0[MAX_TILES];
__device__ int   g_num_tiles;
__device__ int   g_topi[NTOK*TOPK];
__device__ float g_topw[NTOK*TOPK];

// ------------------- helpers -------------------
__device__ __forceinline__ float silu_f(float x){ return x / (1.0f + expf(-x)); }

__device__ __forceinline__ uint32_t smem_u32(const void* p){
    uint32_t a;
    asm("{ .reg .u64 t; cvta.to.shared.u64 t, %1; cvt.u32.u64 %0, t; }" : "=r"(a) : "l"(p));
    return a;
}

#define CP16(dst, src) \
    asm volatile("cp.async.cg.shared.global [%0], [%1], 16;" :: "r"(dst), "l"(src))
#define CP_COMMIT() asm volatile("cp.async.commit_group;")

#define LDSM4(r0,r1,r2,r3, addr) \
    asm volatile("ldmatrix.sync.aligned.m8n8.x4.shared.b16 {%0,%1,%2,%3}, [%4];" \
        : "=r"(r0),"=r"(r1),"=r"(r2),"=r"(r3) : "r"(addr))
#define LDSM2T(r0,r1, addr) \
    asm volatile("ldmatrix.sync.aligned.m8n8.x2.trans.shared.b16 {%0,%1}, [%2];" \
        : "=r"(r0),"=r"(r1) : "r"(addr))

__device__ __forceinline__ void mma_f16(float* d, const uint32_t* a, const uint32_t* b){
    asm volatile(
        "mma.sync.aligned.m16n8k16.row.col.f32.f16.f16.f32 "
        "{%0,%1,%2,%3}, {%4,%5,%6,%7}, {%8,%9}, {%0,%1,%2,%3};"
        : "+f"(d[0]), "+f"(d[1]), "+f"(d[2]), "+f"(d[3])
        : "r"(a[0]), "r"(a[1]), "r"(a[2]), "r"(a[3]), "r"(b[0]), "r"(b[1]));
}

// ------------------- prep: convert x + weights to fp16, init state -------------
__global__ void k_prep(const float* __restrict__ x,
                       const float* __restrict__ wfc_sh,
                       const float* __restrict__ wfc_ex,
                       const float* __restrict__ wpj_sh,
                       const float* __restrict__ wpj_ex){
    int i0 = blockIdx.x*blockDim.x + threadIdx.x;
    int stride = gridDim.x*blockDim.x;
    const size_t NFC = (size_t)CDIM*H2;
    const size_t NPJ = (size_t)HDIM*CDIM;

    for (size_t i = i0; i < (size_t)NTOK*CDIM; i += stride) g_xh[i] = __float2half_rn(x[i]);
    for (size_t i = i0; i < (size_t)NEXP*NFC;  i += stride) g_wfc_h[i] = __float2half_rn(wfc_ex[i]);
    for (size_t i = i0; i < NFC;               i += stride) g_wfc_h[(size_t)NEXP*NFC + i] = __float2half_rn(wfc_sh[i]);
    for (size_t i = i0; i < (size_t)NEXP*NPJ;  i += stride) g_wpj_h[i] = __float2half_rn(wpj_ex[i]);
    for (size_t i = i0; i < NPJ;               i += stride) g_wpj_h[(size_t)NEXP*NPJ + i] = __float2half_rn(wpj_sh[i]);

    for (int i = i0; i < MAX_ROWS; i += stride) g_row_token[i] = 0;
    if (i0 < NEXP) g_counts[i0] = 0;
}

// ------------------- gate: logits, sigmoid, top-4, counts ----------------
__global__ void k_gate(const float* __restrict__ x,
                       const float* __restrict__ wg,
                       const float* __restrict__ bias){
    int warp = (blockIdx.x*blockDim.x + threadIdx.x) >> 5;
    int lane = threadIdx.x & 31;
    if (warp >= NTOK) return;
    const float* xr = x + (size_t)warp*CDIM;

    int e = lane & 15, half = lane >> 4;
    float acc = 0.0f;
    int c0 = half*(CDIM/2);
    for (int c = c0; c < c0 + CDIM/2; ++c) acc += xr[c]*wg[c*NEXP + e];
    acc += __shfl_down_sync(0xFFFFFFFFu, acc, 16);

    float gate = -1.0f;
    if (lane < 16) gate = 1.0f/(1.0f + expf(-(acc + bias[e])));

    int rank = 0;
    #pragma unroll
    for (int j = 0; j < 16; ++j){
        float gj = __shfl_sync(0xFFFFFFFFu, gate, j);
        if (lane < 16) rank += (gj > gate) || (gj == gate && j < e);
    }
    bool sel = (lane < 16) && (rank < TOPK);
    float sv = sel ? gate : 0.0f;
    #pragma unroll
    for (int o = 8; o >= 1; o >>= 1) sv += __shfl_xor_sync(0xFFFFFFFFu, sv, o);
    unsigned ballot = __ballot_sync(0xFFFFFFFFu, sel);
    if (sel){
        int kidx = __popc(ballot & ((1u << lane) - 1u));
        g_topi[warp*TOPK + kidx] = e;
        g_topw[warp*TOPK + kidx] = gate/sv;
        atomicAdd(&g_counts[e], 1);
    }
}

// ------------------- scan + fill fused (single CTA) ----------------
__global__ void __launch_bounds__(1024, 1) k_scanfill(){
    if (threadIdx.x == 0){
        int off = 0, nt = 0;
        for (int e = 0; e <= NEXP; ++e){
            int cnt = (e < NEXP) ? g_counts[e] : NTOK;
            g_offset[e] = off;
            if (e < NEXP) g_cursor[e] = off;
            int tiles = (cnt + TILE_M - 1)/TILE_M;
            for (int i = 0; i < tiles; ++i){
                g_tile_expert[nt] = e;
                g_tile_row0[nt] = off + i*TILE_M;
                nt++;
            }
            off += tiles*TILE_M;
        }
        g_num_tiles = nt;
    }
    __syncthreads();
    for (int idx = threadIdx.x; idx < NTOK*(TOPK+1); idx += 1024){
        int t = idx/(TOPK+1), j = idx%(TOPK+1);
        if (j < TOPK){
            int e = g_topi[t*TOPK + j];
            float w = g_topw[t*TOPK + j];
            int r = atomicAdd(&g_cursor[e], 1);
            g_row_token[r] = t;
            g_row_weight[r] = w;
            g_tok_rows[t*(TOPK+1) + j] = r;
        } else {
            int r = g_offset[NEXP] + t;
            g_row_token[r] = t;
            g_row_weight[r] = 1.0f;
            g_tok_rows[t*(TOPK+1) + j] = r;
        }
    }
}

// ------------------- FC1: swiglu(Xg @ Wfc), fp16 m16n8k16, CTA 128x256 ----------
// 8 warps (2M x 4N), warp tile 64x64. A smem [m][16] fp16 rows 32B, seg-swizzled;
// B smem [k][256] fp16 rows 512B, seg-swizzled; ldmatrix x4 / x2.trans.
__global__ void __launch_bounds__(256, 1) k_fc1(){
    int bx = blockIdx.x;
    int tile = bx / FC1_COLS, jb = (bx % FC1_COLS)*FC1_NOUT;
    if (tile >= g_num_tiles) return;
    int e = g_tile_expert[tile], row0 = g_tile_row0[tile];
    const __half* wbase = g_wfc_h + (size_t)e*CDIM*H2;

    extern __shared__ char smc[];
    uint32_t sb = smem_u32(smc);

    int tid = threadIdx.x, lane = tid & 31, w = tid >> 5;
    int wm = w & 1, wn = w >> 1;
    int m0 = wm*64, n0w = wn*8;     // n-block base (units of 8)
    int r = lane >> 2;

    // cp.async A: thread -> (row am, half-segment ah)
    int am = tid >> 1, ah = tid & 1;
    int tokA = g_row_token[row0 + am];
    const __half* asrc = g_xh + (size_t)tokA*CDIM + ah*8;
    uint32_t adst = (uint32_t)(am*32 + ((ah ^ ((am >> 2) & 1)) << 4));

    // cp.async B: 2 chunks/thread; chunk = (k-row bk, n-block nb)
    const __half* bsrc[2]; uint32_t bdst[2];
    #pragma unroll
    for (int i = 0; i < 2; i++){
        int idx = tid + i*256;
        int bk = idx >> 5, nb = idx & 31;
        int col0 = (nb & 1) ? (HDIM + jb + (nb >> 1)*8) : (jb + (nb >> 1)*8);
        bsrc[i] = wbase + (size_t)bk*H2 + col0;
        bdst[i] = (uint32_t)(A_BYTES + bk*512 + ((nb ^ (bk & 7)) << 4));
    }

    #pragma unroll
    for (int s = 0; s < STAGES-1; s++){
        uint32_t so = sb + s*STG_BYTES;
        CP16(so + adst, asrc + s*KC);
        #pragma unroll
        for (int i = 0; i < 2; i++)
            CP16(so + bdst[i], bsrc[i] + (size_t)s*KC*H2);
        CP_COMMIT();
    }

    float acc[4][8][4];
    #pragma unroll
    for (int i = 0; i < 4; i++)
        #pragma unroll
        for (int j = 0; j < 8; j++)
            #pragma unroll
            for (int q = 0; q < 4; q++) acc[i][j][q] = 0.0f;

    // ldmatrix per-lane offsets
    uint32_t aoff[4];
    {
        int li = lane & 7, msel = (lane >> 3) & 1, h = (lane >> 4) & 1;
        #pragma unroll
        for (int mi = 0; mi < 4; mi++){
            int m = m0 + mi*16 + msel*8 + li;
            aoff[mi] = (uint32_t)(m*32 + ((h ^ ((m >> 2) & 1)) << 4));
        }
    }
    uint32_t boff[8];
    {
        int kk = lane & 15;
        #pragma unroll
        for (int ni = 0; ni < 8; ni++){
            int nb = n0w + ni;
            boff[ni] = (uint32_t)(A_BYTES + kk*512 + ((nb ^ (kk & 7)) << 4));
        }
    }

    const int nK = CDIM/KC;   // 48
    for (int ks = 0; ks < nK; ks++){
        asm volatile("cp.async.wait_group %0;" :: "n"(STAGES-2) : "memory");
        __syncthreads();
        int t = ks + STAGES - 1;
        if (t < nK){
            uint32_t so = sb + (t % STAGES)*STG_BYTES;
            CP16(so + adst, asrc + t*KC);
            #pragma unroll
            for (int i = 0; i < 2; i++)
                CP16(so + bdst[i], bsrc[i] + (size_t)t*KC*H2);
        }
        CP_COMMIT();

        uint32_t st = sb + (ks % STAGES)*STG_BYTES;
        uint32_t a[4][4], b[8][2];
        #pragma unroll
        for (int mi = 0; mi < 4; mi++)
            LDSM4(a[mi][0], a[mi][1], a[mi][2], a[mi][3], st + aoff[mi]);
        #pragma unroll
        for (int ni = 0; ni < 8; ni++)
            LDSM2T(b[ni][0], b[ni][1], st + boff[ni]);
        #pragma unroll
        for (int mi = 0; mi < 4; mi++)
            #pragma unroll
            for (int ni = 0; ni < 8; ni++)
                mma_f16(acc[mi][ni], a[mi], b[ni]);
    }

    // epilogue: swiglu pairs (ni even = gate, ni+1 = val), write fp16
    int c2 = (lane & 3)*2;
    #pragma unroll
    for (int mi = 0; mi < 4; mi++){
        int ra = row0 + m0 + mi*16 + r;
        #pragma unroll
        for (int fe = 0; fe < 8; fe += 2){
            float* ag = acc[mi][fe];
            float* av = acc[mi][fe + 1];
            int ocol = jb + (4*wn + (fe >> 1))*8 + c2;
            __half2 h0 = __floats2half2_rn(silu_f(ag[0])*av[0], silu_f(ag[1])*av[1]);
            __half2 h1 = __floats2half2_rn(silu_f(ag[2])*av[2], silu_f(ag[3])*av[3]);
            *(__half2*)(g_act + (size_t)ra*HDIM + ocol) = h0;
            *(__half2*)(g_act + (size_t)(ra + 8)*HDIM + ocol) = h1;
        }
    }
}

// ------------------- FC2: act @ Wproj -> g_part, fp16 m16n8k16 -------------------
__global__ void __launch_bounds__(256, 1) k_fc2(){
    int bx = blockIdx.x;
    int tile = bx / FC2_COLS, jb = (bx % FC2_COLS)*BLK_N;
    if (tile >= g_num_tiles) return;
    int e = g_tile_expert[tile], row0 = g_tile_row0[tile];
    const __half* wbase = g_wpj_h + (size_t)e*HDIM*CDIM;

    extern __shared__ char smc[];
    uint32_t sb = smem_u32(smc);

    int tid = threadIdx.x, lane = tid & 31, w = tid >> 5;
    int wm = w & 1, wn = w >> 1;
    int m0 = wm*64, n0w = wn*8;
    int r = lane >> 2;

    int am = tid >> 1, ah = tid & 1;
    const __half* asrc = g_act + (size_t)(row0 + am)*HDIM + ah*8;
    uint32_t adst = (uint32_t)(am*32 + ((ah ^ ((am >> 2) & 1)) << 4));

    const __half* bsrc[2]; uint32_t bdst[2];
    #pragma unroll
    for (int i = 0; i < 2; i++){
        int idx = tid + i*256;
        int bk = idx >> 5, nb = idx & 31;
        bsrc[i] = wbase + (size_t)bk*CDIM + jb + nb*8;
        bdst[i] = (uint32_t)(A_BYTES + bk*512 + ((nb ^ (bk & 7)) << 4));
    }

    #pragma unroll
    for (int s = 0; s < STAGES-1; s++){
        uint32_t so = sb + s*STG_BYTES;
        CP16(so + adst, asrc + s*KC);
        #pragma unroll
        for (int i = 0; i < 2; i++)
            CP16(so + bdst[i], bsrc[i] + (size_t)s*KC*CDIM);
        CP_COMMIT();
    }

    float acc[4][8][4];
    #pragma unroll
    for (int i = 0; i < 4; i++)
        #pragma unroll
        for (int j = 0; j < 8; j++)
            #pragma unroll
            for (int q = 0; q < 4; q++) acc[i][j][q] = 0.0f;

    uint32_t aoff[4];
    {
        int li = lane & 7, msel = (lane >> 3) & 1, h = (lane >> 4) & 1;
        #pragma unroll
        for (int mi = 0; mi < 4; mi++){
            int m = m0 + mi*16 + msel*8 + li;
            aoff[mi] = (uint32_t)(m*32 + ((h ^ ((m >> 2) & 1)) << 4));
        }
    }
    uint32_t boff[8];
    {
        int kk = lane & 15;
        #pragma unroll
        for (int ni = 0; ni < 8; ni++){
            int nb = n0w + ni;
            boff[ni] = (uint32_t)(A_BYTES + kk*512 + ((nb ^ (kk & 7)) << 4));
        }
    }

    const int nK = HDIM/KC;   // 192
    for (int ks = 0; ks < nK; ks++){
        asm volatile("cp.async.wait_group %0;" :: "n"(STAGES-2) : "memory");
        __syncthreads();
        int t = ks + STAGES - 1;
        if (t < nK){
            uint32_t so = sb + (t % STAGES)*STG_BYTES;
            CP16(so + adst, asrc + t*KC);
            #pragma unroll
            for (int i = 0; i < 2; i++)
                CP16(so + bdst[i], bsrc[i] + (size_t)t*KC*CDIM);
        }
        CP_COMMIT();

        uint32_t st = sb + (ks % STAGES)*STG_BYTES;
        uint32_t a[4][4], b[8][2];
        #pragma unroll
        for (int mi = 0; mi < 4; mi++)
            LDSM4(a[mi][0], a[mi][1], a[mi][2], a[mi][3], st + aoff[mi]);
        #pragma unroll
        for (int ni = 0; ni < 8; ni++)
            LDSM2T(b[ni][0], b[ni][1], st + boff[ni]);
        #pragma unroll
        for (int mi = 0; mi < 4; mi++)
            #pragma unroll
            for (int ni = 0; ni < 8; ni++)
                mma_f16(acc[mi][ni], a[mi], b[ni]);
    }

    int c2 = (lane & 3)*2;
    #pragma unroll
    for (int mi = 0; mi < 4; mi++){
        int ra = row0 + m0 + mi*16 + r;
        #pragma unroll
        for (int ni = 0; ni < 8; ni++){
            int ocol = jb + wn*64 + ni*8 + c2;
            float2 o0, o1;
            o0.x = acc[mi][ni][0]; o0.y = acc[mi][ni][1];
            o1.x = acc[mi][ni][2]; o1.y = acc[mi][ni][3];
            *(float2*)(g_part + (size_t)ra*CDIM + ocol) = o0;
            *(float2*)(g_part + (size_t)(ra + 8)*CDIM + ocol) = o1;
        }
    }
}

// ------------------- gather: out[t] = sum_j w_j * part[r_j] -------------------
__global__ void k_gather(float* __restrict__ out){
    __shared__ int rs[TOPK+1];
    __shared__ float ws[TOPK+1];
    int t = blockIdx.x;
    if (threadIdx.x < TOPK+1){
        int r = g_tok_rows[t*(TOPK+1) + threadIdx.x];
        rs[threadIdx.x] = r;
        ws[threadIdx.x] = g_row_weight[r];
    }
    __syncthreads();
    int c = threadIdx.x*4;
    float4 acc = make_float4(0.f, 0.f, 0.f, 0.f);
    #pragma unroll
    for (int j = 0; j < TOPK+1; j++){
        const float4 p = *(const float4*)(g_part + (size_t)rs[j]*CDIM + c);
        float w = ws[j];
        acc.x += w*p.x; acc.y += w*p.y; acc.z += w*p.z; acc.w += w*p.w;
    }
    *(float4*)(out + (size_t)t*CDIM + c) = acc;
}

// ------------------- launch -------------------
extern "C" void kernel_launch(void* const* d_in, const int* in_sizes, int n_in,
                              void* d_out, int out_size){
    const float* x              = (const float*)d_in[0];
    const float* w_shared_fc    = (const float*)d_in[1];
    const float* w_shared_proj  = (const float*)d_in[2];
    const float* w_experts_fc   = (const float*)d_in[3];
    const float* w_experts_proj = (const float*)d_in[4];
    const float* w_gate         = (const float*)d_in[5];
    const float* expert_bias    = (const float*)d_in[6];
    float* out = (float*)d_out;

    cudaFuncSetAttribute(k_fc1, cudaFuncAttributeMaxDynamicSharedMemorySize, FC_SMEM);
    cudaFuncSetAttribute(k_fc2, cudaFuncAttributeMaxDynamicSharedMemorySize, FC_SMEM);

    // launch #1: conversions + init fused
    k_prep<<<2368, 256>>>(x, w_shared_fc, w_experts_fc, w_shared_proj, w_experts_proj);
    // launch #2
    k_gate<<<NTOK/8, 256>>>(x, w_gate, expert_bias);
    // launch #3
    k_scanfill<<<1, 1024>>>();
    // launch #4  <- ncu captures this one
    k_fc1<<<MAX_TILES*FC1_COLS, 256, FC_SMEM>>>();
    // launch #5
    k_fc2<<<MAX_TILES*FC2_COLS, 256, FC_SMEM>>>();
    // launch #6
    k_gather<<<NTOK, CDIM/4>>>(out);
}